// round 3
// baseline (speedup 1.0000x reference)
#include <cuda_runtime.h>
#include <cuda_bf16.h>

#define BB 16
#define CC 512
#define TT 8192
#define T_TILE 32
#define NTILES 4096              // 16 rows * 256 tiles
#define NTHREADS 512
#define GRID_P 148
#define DIVC 512.0f
#define EPSV 1e-8f
#define FULL 0xffffffffu

// one 16B record per tile: {s, q, flag, pad}; flag: 0=empty, 1=agg, 2=inclusive prefix
__device__ float4 g_rec[NTILES];

__global__ void init_rec_kernel() {
    int i = blockIdx.x * blockDim.x + threadIdx.x;
    if (i < NTILES) g_rec[i] = make_float4(0.f, 0.f, 0.f, 0.f);
}

__device__ __forceinline__ float4 ld_rec_vol(const float4* p) {
    float4 r;
    asm volatile("ld.volatile.global.v4.f32 {%0,%1,%2,%3}, [%4];"
                 : "=f"(r.x), "=f"(r.y), "=f"(r.z), "=f"(r.w) : "l"(p));
    return r;
}
__device__ __forceinline__ void st_rec_vol(float4* p, float s, float q, int flag) {
    asm volatile("st.volatile.global.v4.f32 [%0], {%1,%2,%3,%4};"
                 :: "l"(p), "f"(s), "f"(q), "f"(__int_as_float(flag)), "f"(0.f)
                 : "memory");
}

// per-thread partial sums over its 8 channels, then reduce the warp's 4 j-values
// -> lanes 0..7 hold per-(4t)-group float4 partials
__device__ __forceinline__ void tile_partials(const float4* v, float4& s4, float4& q4) {
    s4 = make_float4(0.f, 0.f, 0.f, 0.f);
    q4 = make_float4(0.f, 0.f, 0.f, 0.f);
#pragma unroll
    for (int k = 0; k < 8; k++) {
        float4 t = v[k];
        s4.x += t.x; s4.y += t.y; s4.z += t.z; s4.w += t.w;
        q4.x = fmaf(t.x, t.x, q4.x); q4.y = fmaf(t.y, t.y, q4.y);
        q4.z = fmaf(t.z, t.z, q4.z); q4.w = fmaf(t.w, t.w, q4.w);
    }
#pragma unroll
    for (int d = 16; d >= 8; d >>= 1) {
        s4.x += __shfl_down_sync(FULL, s4.x, d); s4.y += __shfl_down_sync(FULL, s4.y, d);
        s4.z += __shfl_down_sync(FULL, s4.z, d); s4.w += __shfl_down_sync(FULL, s4.w, d);
        q4.x += __shfl_down_sync(FULL, q4.x, d); q4.y += __shfl_down_sync(FULL, q4.y, d);
        q4.z += __shfl_down_sync(FULL, q4.z, d); q4.w += __shfl_down_sync(FULL, q4.w, d);
    }
}

__global__ void __launch_bounds__(NTHREADS, 1)
newNormal_kernel(const float* __restrict__ x,
                 const float* __restrict__ gains,
                 const float* __restrict__ bias,
                 float* __restrict__ out) {
    __shared__ float4 part_s[2][15][8];
    __shared__ float4 part_q[2][15][8];
    __shared__ float meanv[T_TILE], invv[T_TILE];

    const int tid  = threadIdx.x;
    const int tg   = tid & 7;      // t-group: t = 4*tg .. 4*tg+3
    const int j    = tid >> 3;     // channels c = j + 64*k
    const int lane = tid & 31;
    const int wid  = tid >> 5;

    float gn[8], bsv[8];
#pragma unroll
    for (int k = 0; k < 8; k++) {
        gn[k]  = __ldg(gains + j + 64 * k);
        bsv[k] = __ldg(bias  + j + 64 * k);
    }

    float4 cur[8], nxt[8];

    int g = blockIdx.x;
    {
        const int b = g >> 8, tile = g & 255;
        const float* p = x + ((size_t)b * CC + j) * TT + tile * T_TILE + 4 * tg;
#pragma unroll
        for (int k = 0; k < 8; k++)
            cur[k] = __ldcs((const float4*)(p + (size_t)(64 * k) * TT));
    }

    // prologue: workers stash partials of first tile into buffer 0
    if (wid) {
        float4 s4, q4;
        tile_partials(cur, s4, q4);
        if (lane < 8) { part_s[0][wid - 1][lane] = s4; part_q[0][wid - 1][lane] = q4; }
    }
    __syncthreads();

    int buf = 0;
    for (; g < NTILES; g += GRID_P) {
        const int b    = g >> 8;
        const int tile = g & 255;
        const int t0   = tile * T_TILE;
        const int gnx  = g + GRID_P;

        // ---- prefetch next tile (all threads) ----
        if (gnx < NTILES) {
            const int b2 = gnx >> 8, tl2 = gnx & 255;
            const float* p = x + ((size_t)b2 * CC + j) * TT + tl2 * T_TILE + 4 * tg;
#pragma unroll
            for (int k = 0; k < 8; k++)
                nxt[k] = __ldcs((const float4*)(p + (size_t)(64 * k) * TT));
        }

        if (wid == 0) {
            // ---- scanner: own partials of cur + workers' partials from last iter ----
            float4 s4, q4;
            tile_partials(cur, s4, q4);
            if (lane < 8) {
#pragma unroll
                for (int w = 0; w < 15; w++) {
                    float4 a = part_s[buf][w][lane];
                    s4.x += a.x; s4.y += a.y; s4.z += a.z; s4.w += a.w;
                    float4 c = part_q[buf][w][lane];
                    q4.x += c.x; q4.y += c.y; q4.z += c.z; q4.w += c.w;
                }
            }
            // in-register inclusive scan within each group of 4 t
            float4 is, iq;
            is.x = s4.x; is.y = is.x + s4.y; is.z = is.y + s4.z; is.w = is.z + s4.w;
            iq.x = q4.x; iq.y = iq.x + q4.y; iq.z = iq.y + q4.z; iq.w = iq.z + q4.w;
            // scan group totals across lanes 0..7
            float gs = is.w, gq = iq.w;
            float ssc = gs, qsc = gq;
#pragma unroll
            for (int d = 1; d < 8; d <<= 1) {
                float a = __shfl_up_sync(FULL, ssc, d, 8);
                float c = __shfl_up_sync(FULL, qsc, d, 8);
                if ((lane & 7) >= d && lane < 8) { ssc += a; qsc += c; }
            }
            const float exg_s = ssc - gs, exg_q = qsc - gq;
            const float tot_s = __shfl_sync(FULL, ssc, 7);
            const float tot_q = __shfl_sync(FULL, qsc, 7);

            // ---- decoupled look-back (warp-parallel, 32 records/round) ----
            float ex_s = 0.f, ex_q = 0.f;
            if (tile == 0) {
                if (lane == 0) st_rec_vol(&g_rec[g], tot_s, tot_q, 2);
            } else {
                if (lane == 0) st_rec_vol(&g_rec[g], tot_s, tot_q, 1);
                const int base = g & ~255;
                int p_hi = g - 1;
                for (;;) {
                    const int p = p_hi - lane;
                    float rs, rq; int f;
                    if (p >= base) {
                        float4 r = ld_rec_vol(&g_rec[p]);
                        rs = r.x; rq = r.y; f = __float_as_int(r.z);
                    } else { rs = 0.f; rq = 0.f; f = 2; }
                    if (__ballot_sync(FULL, f == 0)) { __nanosleep(32); continue; }
                    const unsigned m2 = __ballot_sync(FULL, f == 2);
                    if (m2) {
                        const int l2 = __ffs(m2) - 1;
                        float cs = (lane <= l2) ? rs : 0.f;
                        float cq = (lane <= l2) ? rq : 0.f;
#pragma unroll
                        for (int d = 16; d; d >>= 1) {
                            cs += __shfl_down_sync(FULL, cs, d);
                            cq += __shfl_down_sync(FULL, cq, d);
                        }
                        ex_s += __shfl_sync(FULL, cs, 0);
                        ex_q += __shfl_sync(FULL, cq, 0);
                        break;
                    } else {
                        float cs = rs, cq = rq;
#pragma unroll
                        for (int d = 16; d; d >>= 1) {
                            cs += __shfl_down_sync(FULL, cs, d);
                            cq += __shfl_down_sync(FULL, cq, d);
                        }
                        ex_s += __shfl_sync(FULL, cs, 0);
                        ex_q += __shfl_sync(FULL, cq, 0);
                        p_hi -= 32;
                    }
                }
                if (lane == 0) st_rec_vol(&g_rec[g], ex_s + tot_s, ex_q + tot_q, 2);
            }

            // ---- mean / rsqrt (lanes 0..7, one float4 of t each) ----
            if (lane < 8) {
                const float bs = ex_s + exg_s;
                const float bq = ex_q + exg_q;
                const int tg4 = t0 + 4 * lane;
                float4 m4, i4;
                {
                    float dv = 1.0f / ((float)(tg4 + 1) * DIVC);
                    float m = (bs + is.x) * dv;
                    float var = fmaf(-m, m, (bq + iq.x) * dv);
                    m4.x = m; i4.x = rsqrtf(var + EPSV);
                }
                {
                    float dv = 1.0f / ((float)(tg4 + 2) * DIVC);
                    float m = (bs + is.y) * dv;
                    float var = fmaf(-m, m, (bq + iq.y) * dv);
                    m4.y = m; i4.y = rsqrtf(var + EPSV);
                }
                {
                    float dv = 1.0f / ((float)(tg4 + 3) * DIVC);
                    float m = (bs + is.z) * dv;
                    float var = fmaf(-m, m, (bq + iq.z) * dv);
                    m4.z = m; i4.z = rsqrtf(var + EPSV);
                }
                {
                    float dv = 1.0f / ((float)(tg4 + 4) * DIVC);
                    float m = (bs + is.w) * dv;
                    float var = fmaf(-m, m, (bq + iq.w) * dv);
                    m4.w = m; i4.w = rsqrtf(var + EPSV);
                }
                *(float4*)&meanv[4 * lane] = m4;
                *(float4*)&invv[4 * lane]  = i4;
            }
        } else if (gnx < NTILES) {
            // ---- workers: partials of NEXT tile (stall overlaps scanner look-back) ----
            float4 s4, q4;
            tile_partials(nxt, s4, q4);
            if (lane < 8) { part_s[buf ^ 1][wid - 1][lane] = s4; part_q[buf ^ 1][wid - 1][lane] = q4; }
        }
        __syncthreads();

        // ---- normalize cur + store (all threads) ----
        {
            const float4 m4 = *(const float4*)&meanv[4 * tg];
            const float4 i4 = *(const float4*)&invv[4 * tg];
            float* po = out + ((size_t)b * CC + j) * TT + t0 + 4 * tg;
#pragma unroll
            for (int k = 0; k < 8; k++) {
                float4 v = cur[k];
                float4 o;
                o.x = fmaf((v.x - m4.x) * i4.x, gn[k], bsv[k]);
                o.y = fmaf((v.y - m4.y) * i4.y, gn[k], bsv[k]);
                o.z = fmaf((v.z - m4.z) * i4.z, gn[k], bsv[k]);
                o.w = fmaf((v.w - m4.w) * i4.w, gn[k], bsv[k]);
                __stcs((float4*)(po + (size_t)(64 * k) * TT), o);
            }
        }

#pragma unroll
        for (int k = 0; k < 8; k++) cur[k] = nxt[k];
        buf ^= 1;
    }
}

extern "C" void kernel_launch(void* const* d_in, const int* in_sizes, int n_in,
                              void* d_out, int out_size) {
    (void)in_sizes; (void)n_in; (void)out_size;
    const float* x     = (const float*)d_in[0];
    const float* gains = (const float*)d_in[1];
    const float* bias  = (const float*)d_in[2];
    float* out = (float*)d_out;

    init_rec_kernel<<<(NTILES + 255) / 256, 256>>>();
    newNormal_kernel<<<GRID_P, NTHREADS>>>(x, gains, bias, out);
}